// round 13
// baseline (speedup 1.0000x reference)
#include <cuda_runtime.h>
#include <cstdint>
#include <math.h>

#define HWD 96
#define NB 8

__device__ float g_cat[(size_t)NB*320*HWD*HWD];
__device__ float g_h1s[(size_t)NB*128*HWD*HWD];
__device__ float g_h1m[(size_t)NB*128*HWD*HWD];
__device__ float g_h1w[(size_t)NB*128*HWD*HWD];
__device__ float g_h2s[(size_t)NB*128*HWD*HWD];
__device__ float g_h2m[(size_t)NB*128*HWD*HWD];
__device__ float g_ww2[(size_t)NB*576*HWD*HWD];
__device__ float g_gmax[NB*576];
__device__ float g_wt[10035200];   // frag-ordered, tf32-rounded weights

// ---------- helpers ----------
__device__ __forceinline__ float to_tf32(float x){ float r; asm("cvt.rna.tf32.f32 %0,%1;":"=f"(r):"f"(x)); return r; }

#define CPA8(d,s)   asm volatile("cp.async.ca.shared.global [%0],[%1],8;"::"r"(d),"l"(s):"memory")
#define CPA16(d,s)  asm volatile("cp.async.ca.shared.global [%0],[%1],16;"::"r"(d),"l"(s):"memory")
#define CP_COMMIT() asm volatile("cp.async.commit_group;":::"memory")
#define CP_WAITG0() asm volatile("cp.async.wait_group 0;":::"memory")

__device__ __forceinline__ uint32_t smem_u32(const void* p){
    uint32_t a; asm("{ .reg .u64 t; cvta.to.shared.u64 t, %1; cvt.u32.u64 %0, t; }":"=r"(a):"l"(p)); return a;
}

// tf32 m16n8k8 mma.sync (sm_80+ portable PTX -> tensor pipe)
__device__ __forceinline__ void mma8(float* c, const uint32_t* a, uint32_t b0, uint32_t b1){
    asm volatile("mma.sync.aligned.m16n8k8.row.col.f32.tf32.tf32.f32 "
        "{%0,%1,%2,%3},{%4,%5,%6,%7},{%8,%9},{%0,%1,%2,%3};"
        : "+f"(c[0]),"+f"(c[1]),"+f"(c[2]),"+f"(c[3])
        : "r"(a[0]),"r"(a[1]),"r"(a[2]),"r"(a[3]),"r"(b0),"r"(b1));
}

// ---------- upsample+concat (tf32 rounded) ----------
__global__ void upcat_kernel(const float* __restrict__ z2, const float* __restrict__ y1, float* __restrict__ cat){
    long idx = (long)blockIdx.x*blockDim.x + threadIdx.x;
    const long total = (long)NB*320*HWD*HWD;
    if(idx>=total) return;
    int X=(int)(idx%HWD); long t=idx/HWD; int Y=(int)(t%HWD); t/=HWD; int c=(int)(t%320); int b=(int)(t/320);
    float v;
    if(c<128){
        const float S=23.0f/95.0f; float fy=Y*S, fx=X*S;
        int y0=(int)fy, x0=(int)fx; int y1i=min(y0+1,23), x1i=min(x0+1,23);
        float wy=fy-(float)y0, wx=fx-(float)x0;
        const float* p = z2 + ((size_t)(b*128+c)*24)*24;
        float a=p[y0*24+x0], bq=p[y0*24+x1i], cq=p[y1i*24+x0], dq=p[y1i*24+x1i];
        float top=a*(1.f-wx)+bq*wx, bot=cq*(1.f-wx)+dq*wx;
        v = top*(1.f-wy)+bot*wy;
    } else v = y1[((size_t)(b*192+(c-128))*HWD+Y)*HWD+X];
    cat[idx] = to_tf32(v);
}

// ---------- merged weight prep (all 8 layers, one launch) ----------
struct WT8 {
    const float* w[8];
    long off[8];
    long recEnd[8];
    int cin[8], KG[8], MBt[8];
};
__global__ void wtrans_all(WT8 T, float* __restrict__ wt, long totalThr){
    long idx = (long)blockIdx.x*blockDim.x + threadIdx.x;
    if(idx >= totalThr) return;
    int l = (int)(idx&31); long rec = idx>>5;
    int L = 0;
    while(rec >= T.recEnd[L]) L++;
    long rl = rec - (L ? T.recEnd[L-1] : 0);
    const int MBt = T.MBt[L], KG = T.KG[L], cin = T.cin[L];
    int mb = (int)(rl % MBt); long r2 = rl / MBt;
    int kg = (int)(r2 % KG); int tap = (int)(r2 / KG);
    const float* w = T.w[L];
    int oc = mb*16 + (l>>2), c = kg*8 + (l&3);
    float4 v;
    v.x = to_tf32(w[((size_t)oc*cin + c)*25 + tap]);
    v.y = to_tf32(w[((size_t)(oc+8)*cin + c)*25 + tap]);
    v.z = to_tf32(w[((size_t)oc*cin + c+4)*25 + tap]);
    v.w = to_tf32(w[((size_t)(oc+8)*cin + c+4)*25 + tap]);
    reinterpret_cast<float4*>(wt + T.off[L] + rl*128)[l] = v;
}

// ---------- table-driven conv stage ----------
struct ConvSlice {
    const float* in;     // input feature map base
    float*       outp;   // output feature map base
    const float* wrec;   // frag-ordered weights for this layer
    const float* bias;
    int mb0;             // first m16 record (= octile*2, 32-oc tiles)
    int MBt;             // records per (tap,kg) row = cout/16
    int cout;            // logical output channels (stride of out tensor)
    int actrnd;          // act | (rnd<<4); act: 0 none, 1 relu, 2 lrelu
};
struct ConvTable { ConvSlice s[36]; };

// Block: 128 thr = 4 warps; warp wy covers output row y0+wy, all 96 x, 32 oc (2 m16 tiles).
// smem: [0..20480) weight dbuf (2 x 10KB = 5 taps x 20 records), [20480..) act 16 planes x 840 words.
// 3 blocks/SM -> 12 warps/SM (latency hiding for the B-fragment LDS chains).
template<int CINL>
__global__ void __launch_bounds__(128,3)
conv5_stage(ConvTable T){
    extern __shared__ __align__(16) char smem[];
    float* wsm  = reinterpret_cast<float*>(smem);            // 2 x 2560 floats
    float* actm = reinterpret_cast<float*>(smem + 20480);    // 16*840 floats
    const uint32_t wsmA  = smem_u32(wsm);
    const uint32_t actmA = smem_u32(actm);

    const ConvSlice S = T.s[blockIdx.z];
    const int tid = threadIdx.x, lane = tid&31, wy = tid>>5;
    const int y0 = blockIdx.x*4, b = blockIdx.y;
    const int mb0 = S.mb0, MBt = S.MBt;
    constexpr int KG = CINL/8;

    float acc[2][12][4];
#pragma unroll
    for(int m=0;m<2;m++)
#pragma unroll
        for(int n=0;n<12;n++)
#pragma unroll
            for(int k=0;k<4;k++) acc[m][n][k]=0.f;

    const float* inB = S.in + (size_t)b*CINL*(HWD*HWD);
    const float* wrec = S.wrec;

    for(int ch=0; ch<CINL/16; ch++){
        // ---- fill act: thread = (kc, irow); plane stride 840 words ----
        {
            int kc = tid>>3, irow = tid&7;
            int gy = y0 + irow - 2;
            uint32_t dst = actmA + (uint32_t)(kc*840 + irow*104)*4;
            if((unsigned)gy < 96u){
                asm volatile("st.shared.v2.b32 [%0],{%1,%1};"::"r"(dst),"r"(0):"memory");
                asm volatile("st.shared.v2.b32 [%0],{%1,%1};"::"r"(dst+392),"r"(0):"memory");
                asm volatile("st.shared.v2.b32 [%0],{%1,%1};"::"r"(dst+400),"r"(0):"memory");
                asm volatile("st.shared.v2.b32 [%0],{%1,%1};"::"r"(dst+408),"r"(0):"memory");
                const float* src = inB + ((size_t)(ch*16+kc)*HWD + gy)*HWD;
#pragma unroll
                for(int j=0;j<48;j++) CPA8(dst + 8 + j*8, src + j*2);
            } else {
#pragma unroll
                for(int j=0;j<26;j++)
                    asm volatile("st.shared.v4.b32 [%0],{%1,%1,%1,%1};"::"r"(dst+j*16),"r"(0):"memory");
            }
        }
        // ---- stage group 0 weights (taps 0..4) into buf 0: 640 float4 tasks ----
        {
#pragma unroll
            for(int i=0;i<5;i++){
                int f4 = tid + i*128;
                int rec = f4>>5, l = f4&31;           // rec = tloc*4 + kg2*2 + mb
                int tloc = rec>>2, r4 = rec&3;
                int kg2 = r4>>1, mb = r4&1;
                const float* gs = wrec + (((size_t)(tloc)*KG + ch*2 + kg2)*MBt + mb0 + mb)*128 + l*4;
                CPA16(wsmA + (uint32_t)(rec*512 + l*16), gs);
            }
        }
        CP_COMMIT(); CP_WAITG0();
        __syncthreads();

        for(int grp=0; grp<5; grp++){
            const int buf = grp&1;
            if(grp<4){
#pragma unroll
                for(int i=0;i<5;i++){
                    int f4 = tid + i*128;
                    int rec = f4>>5, l = f4&31;
                    int tloc = rec>>2, r4 = rec&3;
                    int kg2 = r4>>1, mb = r4&1;
                    const float* gs = wrec + (((size_t)((grp+1)*5 + tloc)*KG + ch*2 + kg2)*MBt + mb0 + mb)*128 + l*4;
                    CPA16(wsmA + (uint32_t)((1-buf)*10240 + rec*512 + l*16), gs);
                }
                CP_COMMIT();
            }
#pragma unroll
            for(int tloc=0; tloc<5; tloc++){
#pragma unroll
                for(int kg2=0; kg2<2; kg2++){
                    uint32_t A[2][4];
#pragma unroll
                    for(int m=0;m<2;m++){
                        const uint4 av = reinterpret_cast<const uint4*>(
                            wsm + buf*2560 + (tloc*4 + kg2*2 + m)*128)[lane];
                        A[m][0]=av.x; A[m][1]=av.y; A[m][2]=av.z; A[m][3]=av.w;
                    }
                    const float* ap = actm + (kg2*8 + (lane&3))*840 + (wy+grp)*104 + (lane>>2) + tloc;
#pragma unroll
                    for(int nb=0; nb<12; nb++){
                        uint32_t b0 = __float_as_uint(ap[nb*8]);
                        uint32_t b1 = __float_as_uint(ap[nb*8 + 3360]);
#pragma unroll
                        for(int m=0;m<2;m++) mma8(acc[m][nb], A[m], b0, b1);
                    }
                }
            }
            if(grp<4) CP_WAITG0();
            __syncthreads();
        }
    }

    // ---- epilogue (runtime act/rnd) ----
    const int act = S.actrnd & 15, rnd = S.actrnd >> 4;
    const int coutR = S.cout, oc0 = mb0*16;
#pragma unroll
    for(int m=0;m<2;m++){
        int ocm = oc0 + m*16 + (lane>>2);
#pragma unroll
        for(int h=0;h<2;h++){
            int oc = ocm + h*8;
            if(oc < coutR){
                float bv = S.bias[oc];
                float* row = S.outp + ((size_t)(b*coutR + oc)*HWD + (y0+wy))*HWD;
#pragma unroll
                for(int nb=0; nb<12; nb++){
                    float c0 = acc[m][nb][h*2+0] + bv;
                    float c1 = acc[m][nb][h*2+1] + bv;
                    if(act==1){ c0=fmaxf(c0,0.f); c1=fmaxf(c1,0.f); }
                    else if(act==2){ c0=(c0>=0.f)?c0:0.01f*c0; c1=(c1>=0.f)?c1:0.01f*c1; }
                    if(rnd){ c0=to_tf32(c0); c1=to_tf32(c1); }
                    *reinterpret_cast<float2*>(row + nb*8 + (lane&3)*2) = make_float2(c0,c1);
                }
            }
        }
    }
}

// ---------- global max ----------
__global__ void maxred_kernel(const float* __restrict__ x, float* __restrict__ gmax){
    __shared__ float sm[256];
    int bc=blockIdx.x;
    const float* p = x + (size_t)bc*HWD*HWD;
    float m=-3.402823466e38f;
    for(int i=threadIdx.x;i<HWD*HWD;i+=256) m=fmaxf(m,p[i]);
    sm[threadIdx.x]=m; __syncthreads();
    for(int st=128;st>0;st>>=1){ if(threadIdx.x<st) sm[threadIdx.x]=fmaxf(sm[threadIdx.x],sm[threadIdx.x+st]); __syncthreads(); }
    if(threadIdx.x==0) gmax[bc]=sm[0];
}

// ---------- lrelu -> 1x1 conv 576 -> grouped softmax ----------
__global__ void weights_kernel(const float* __restrict__ gmax, const float* __restrict__ ww3,
                               const float* __restrict__ bw3, float* __restrict__ outw){
    __shared__ float gsm[576]; __shared__ float osm[576];
    int b=blockIdx.x, t=threadIdx.x;
    float x=gmax[b*576+t];
    gsm[t]=(x>=0.f)?x:0.01f*x;
    __syncthreads();
    float a=bw3[t];
    const float* wr=ww3+(size_t)t*576;
    for(int i=0;i<576;i++) a=fmaf(wr[i],gsm[i],a);
    osm[t]=a; __syncthreads();
    if(t<192){
        float p=osm[t],q=osm[192+t],r=osm[384+t];
        float mx=fmaxf(p,fmaxf(q,r));
        float ep=expf(p-mx),eq=expf(q-mx),er=expf(r-mx);
        float inv=1.f/(ep+eq+er);
        outw[b*576+t]=ep*inv; outw[b*576+192+t]=eq*inv; outw[b*576+384+t]=er*inv;
    }
}

// ---------- launch ----------
static const int CONV_SMEM = 20480 + 16*840*4;   // 74240

extern "C" void kernel_launch(void* const* d_in, const int* in_sizes, int n_in, void* d_out, int out_size){
    const float* z2=(const float*)d_in[0];  const float* y1=(const float*)d_in[1];
    const float* ws1=(const float*)d_in[2]; const float* bs1=(const float*)d_in[3];
    const float* ws2=(const float*)d_in[4]; const float* bs2=(const float*)d_in[5];
    const float* ws3=(const float*)d_in[6]; const float* bs3=(const float*)d_in[7];
    const float* wm1=(const float*)d_in[8]; const float* bm1=(const float*)d_in[9];
    const float* wm2=(const float*)d_in[10];const float* bm2=(const float*)d_in[11];
    const float* wm3=(const float*)d_in[12];const float* bm3=(const float*)d_in[13];
    const float* ww1=(const float*)d_in[14];const float* bw1=(const float*)d_in[15];
    const float* ww2=(const float*)d_in[16];const float* bw2=(const float*)d_in[17];
    const float* ww3=(const float*)d_in[18];const float* bw3=(const float*)d_in[19];
    float* out=(float*)d_out;

    float *cat,*h1s,*h1m,*h1w,*h2s,*h2m,*ww2o,*gmax,*wtb;
    cudaGetSymbolAddress((void**)&cat,g_cat);
    cudaGetSymbolAddress((void**)&h1s,g_h1s);
    cudaGetSymbolAddress((void**)&h1m,g_h1m);
    cudaGetSymbolAddress((void**)&h1w,g_h1w);
    cudaGetSymbolAddress((void**)&h2s,g_h2s);
    cudaGetSymbolAddress((void**)&h2m,g_h2m);
    cudaGetSymbolAddress((void**)&ww2o,g_ww2);
    cudaGetSymbolAddress((void**)&gmax,g_gmax);
    cudaGetSymbolAddress((void**)&wtb,g_wt);

    cudaFuncSetAttribute(conv5_stage<320>, cudaFuncAttributeMaxDynamicSharedMemorySize, CONV_SMEM);
    cudaFuncSetAttribute(conv5_stage<128>, cudaFuncAttributeMaxDynamicSharedMemorySize, CONV_SMEM);

    const size_t MEA_OFF=(size_t)NB*576*HWD*HWD;
    const size_t WGT_OFF=2*MEA_OFF;

    const long O_S1=0, O_M1=1024000, O_W1=2048000, O_S2=3072000, O_M2=3481600,
               O_S3=3891200, O_M3=5734400, O_W2=7577600;
    {
        WT8 T;
        const float* ws[8] = {ws1,wm1,ww1,ws2,wm2,ws3,wm3,ww2};
        long offs[8]   = {O_S1,O_M1,O_W1,O_S2,O_M2,O_S3,O_M3,O_W2};
        int cins[8]    = {320,320,320,128,128,128,128,128};
        int couts[8]   = {128,128,128,128,128,576,576,576};
        long cum = 0;
        for(int i=0;i<8;i++){
            T.w[i]=ws[i]; T.off[i]=offs[i]; T.cin[i]=cins[i];
            T.KG[i]=cins[i]/8; T.MBt[i]=couts[i]/16;
            cum += 25L*T.KG[i]*T.MBt[i];
            T.recEnd[i]=cum;
        }
        long totalThr = cum*32;
        wtrans_all<<<(int)((totalThr+255)/256),256>>>(T, wtb, totalThr);
    }

    { long tot=(long)NB*320*HWD*HWD; upcat_kernel<<<(int)((tot+255)/256),256>>>(z2,y1,cat); }

    dim3 blk(128);
    auto mkslice=[](const float* in, float* outp, const float* wr, const float* bi,
                    int octile, int cout, int act, int rnd){
        ConvSlice s; s.in=in; s.outp=outp; s.wrec=wr; s.bias=bi;
        s.mb0=octile*2; s.MBt=cout/16; s.cout=cout; s.actrnd=act|(rnd<<4); return s;
    };

    // stage 1: s1,m1,w1 (CIN=320, cout=128) -> 12 slices (32-oc tiles)
    {
        ConvTable T;
        int z=0;
        for(int ot=0; ot<4; ot++) T.s[z++]=mkslice(cat,h1s,wtb+O_S1,bs1,ot,128,1,1);
        for(int ot=0; ot<4; ot++) T.s[z++]=mkslice(cat,h1m,wtb+O_M1,bm1,ot,128,2,1);
        for(int ot=0; ot<4; ot++) T.s[z++]=mkslice(cat,h1w,wtb+O_W1,bw1,ot,128,2,1);
        conv5_stage<320><<<dim3(24,NB,12),blk,CONV_SMEM>>>(T);
    }
    // stage 2: s2,m2,ww2conv (CIN=128) -> 26 slices
    {
        ConvTable T;
        int z=0;
        for(int ot=0; ot<4; ot++) T.s[z++]=mkslice(h1s,h2s,wtb+O_S2,bs2,ot,128,1,1);
        for(int ot=0; ot<4; ot++) T.s[z++]=mkslice(h1m,h2m,wtb+O_M2,bm2,ot,128,2,1);
        for(int ot=0; ot<18; ot++) T.s[z++]=mkslice(h1w,ww2o,wtb+O_W2,bw2,ot,576,0,0);
        conv5_stage<128><<<dim3(24,NB,26),blk,CONV_SMEM>>>(T);
    }
    // maxred here so a conv stage lands on the ncu -s 5 -c 1 capture slot
    maxred_kernel<<<NB*576,256>>>(ww2o,gmax);
    // stage 3: s3,m3 (CIN=128, cout=576) -> 36 slices
    {
        ConvTable T;
        int z=0;
        for(int ot=0; ot<18; ot++) T.s[z++]=mkslice(h2s,out,wtb+O_S3,bs3,ot,576,1,0);
        for(int ot=0; ot<18; ot++) T.s[z++]=mkslice(h2m,out+MEA_OFF,wtb+O_M3,bm3,ot,576,0,0);
        conv5_stage<128><<<dim3(24,NB,36),blk,CONV_SMEM>>>(T);
    }
    weights_kernel<<<NB,576>>>(gmax,ww3,bw3,out+WGT_OFF);
}